// round 13
// baseline (speedup 1.0000x reference)
#include <cuda_runtime.h>
#include <cuda_bf16.h>
#include <cstdint>

// ============================================================================
// ScaledDotProductAttention B=2, S=4096, E=1024 — mma.sync bf16 split-precision
// x = hi + lo (bf16);  A*B ~= Ah*Bh + Ah*Bl + Al*Bh  with fp32 accumulators.
// All GEMMs NT: C[m,n] = sum_k A[m,k] * B[n,k], operands row-major bf16 hi/lo.
// R11: mainloop is crossbar-BYTE-bound (R8: 1412 cyc/kc vs 1344 theoretical).
// Cut read duplication: 8 warps of 32x64 (A-dup 2, B-dup 4 -> 96KB reads/kc
// vs 128KB), restore 16 warps/SM via 2 CTAs/SM (2-stage kc32, 80KB SMEM/CTA,
// __launch_bounds__(256,2)). R10's KC64 2-stage reverted (refill slack + ptxas
// de-pipelining). cp.async visibility rule (R6): reads only after the barrier
// that follows the covering wait_group.
// ============================================================================

#define SQ    4096
#define EMB   1024
#define NB    2
#define NINF  -1000000000.0f
#define SCALE 0.03125f

#define APS ((size_t)8192 * 1024 * 2)   // one packed activation tensor
#define WPS ((size_t)1024 * 1024 * 2)   // one packed weight tensor

// ---------------- scratch (device globals; no allocation allowed) -----------
__device__ uint8_t g_pah[3 * APS];                    // packed q,k,v inputs (hi)
__device__ uint8_t g_pal[3 * APS];                    // (lo)
__device__ uint8_t g_pwh[3 * WPS];                    // packed Wq,Wk,Wv (hi)
__device__ uint8_t g_pwl[3 * WPS];                    // (lo)
__device__ uint8_t g_q_hi [APS];
__device__ uint8_t g_q_lo [APS];
__device__ uint8_t g_k_hi [APS];
__device__ uint8_t g_k_lo [APS];
__device__ uint8_t g_vt_hi[(size_t)2048 * 4096 * 2];  // v^T: row = b*1024+n, col = s
__device__ uint8_t g_vt_lo[(size_t)2048 * 4096 * 2];
__device__ float   g_sc   [(size_t)NB * SQ * SQ];     // fp32 masked scaled scores
__device__ float   g_bmax [(size_t)NB * SQ * 32];     // per-row per-128col-block max
__device__ float   g_rsum [(size_t)NB * SQ];          // per-row sum of exp
__device__ uint8_t g_at_hi[(size_t)8192 * 4096 * 2];  // packed unnormalized exp
__device__ uint8_t g_at_lo[(size_t)8192 * 4096 * 2];

// ---------------- helpers ----------------------------------------------------
__device__ __forceinline__ uint32_t smem_u32(const void* p) {
    uint32_t a;
    asm("{ .reg .u64 t; cvta.to.shared.u64 t, %1; cvt.u32.u64 %0, t; }" : "=r"(a) : "l"(p));
    return a;
}

__device__ __forceinline__ void cp16(uint32_t dst, const void* src) {
    asm volatile("cp.async.cg.shared.global [%0], [%1], 16;" :: "r"(dst), "l"(src));
}

__device__ __forceinline__ void ldsm4(uint32_t r[4], uint32_t addr) {
    asm volatile("ldmatrix.sync.aligned.m8n8.x4.shared.b16 {%0,%1,%2,%3}, [%4];"
        : "=r"(r[0]), "=r"(r[1]), "=r"(r[2]), "=r"(r[3]) : "r"(addr));
}

__device__ __forceinline__ void mma16816(float* c, const uint32_t a[4],
                                         uint32_t b0, uint32_t b1) {
    asm volatile("mma.sync.aligned.m16n8k16.row.col.f32.bf16.bf16.f32 "
        "{%0,%1,%2,%3}, {%4,%5,%6,%7}, {%8,%9}, {%0,%1,%2,%3};"
        : "+f"(c[0]), "+f"(c[1]), "+f"(c[2]), "+f"(c[3])
        : "r"(a[0]), "r"(a[1]), "r"(a[2]), "r"(a[3]), "r"(b0), "r"(b1));
}

__device__ __forceinline__ void split4(const float* v, unsigned long long& H,
                                       unsigned long long& L) {
    unsigned long long h = 0, l = 0;
#pragma unroll
    for (int i = 0; i < 4; ++i) {
        __nv_bfloat16 hb = __float2bfloat16(v[i]);
        float hf = __bfloat162float(hb);
        __nv_bfloat16 lb = __float2bfloat16(v[i] - hf);
        unsigned short hs = *reinterpret_cast<unsigned short*>(&hb);
        unsigned short ls = *reinterpret_cast<unsigned short*>(&lb);
        h |= (unsigned long long)hs << (16 * i);
        l |= (unsigned long long)ls << (16 * i);
    }
    H = h; L = l;
}

// ---------------- fused pack: 3 fp32 tensors -> bf16 hi/lo row-major ---------
__global__ void __launch_bounds__(256)
pack3(const float* __restrict__ s0, const float* __restrict__ s1, const float* __restrict__ s2,
      uint8_t* __restrict__ hiB, uint8_t* __restrict__ loB, size_t sliceBytes, int blocksPer)
{
    const int which = blockIdx.x / blocksPer;
    const int blk   = blockIdx.x - which * blocksPer;
    const float* src = (which == 0) ? s0 : (which == 1) ? s1 : s2;
    uint8_t* hi = hiB + (size_t)which * sliceBytes;
    uint8_t* lo = loB + (size_t)which * sliceBytes;
    size_t idx = ((size_t)blk * 256 + threadIdx.x) * 4;
    float4 x = *(const float4*)(src + idx);
    float v[4] = {x.x, x.y, x.z, x.w};
    unsigned long long H, L;
    split4(v, H, L);
    *(unsigned long long*)(hi + idx * 2) = H;
    *(unsigned long long*)(lo + idx * 2) = L;
}

// ---------------- the mma.sync GEMM mainloop ---------------------------------
// SMEM: 2 stages x 4 tiles (Ah, Al, Bh, Bl), tile = 128 rows x 80B (64B data,
// K-chunk 32). 80B row stride keeps ldmatrix conflict-free. 80KB/CTA -> 2 CTAs/SM.
#define TILE_B  10240
#define STG     40960
#define SMEM_SZ 81920
#define NTHR    256

__device__ __forceinline__ void load_stage(
    uint32_t sb, int slot, int tid, int kc, int K,
    const uint8_t* aHi, const uint8_t* aLo,
    const uint8_t* bHi, const uint8_t* bLo,
    size_t aOff, size_t bOff)
{
    const uint32_t so = sb + (uint32_t)slot * STG;
#pragma unroll
    for (int j = 0; j < 2; ++j) {
        const int i = tid + j * 256;      // 512 chunks of 16B per tile
        const int r = i >> 2, c = i & 3;
        const uint32_t soff = (uint32_t)(r * 80 + c * 16);
        const size_t goff = ((size_t)r * K + (size_t)kc * 32 + c * 8) * 2;
        cp16(so + soff,              aHi + aOff + goff);
        cp16(so + TILE_B + soff,     aLo + aOff + goff);
        cp16(so + 2 * TILE_B + soff, bHi + bOff + goff);
        cp16(so + 3 * TILE_B + soff, bLo + bOff + goff);
    }
    asm volatile("cp.async.commit_group;" ::: "memory");
}

// 8 warps, warp grid 4(m) x 2(n), warp tile 32x64.
struct Frags { uint32_t ah[2][4], al[2][4], bh[4][4], bl[4][4]; };

__device__ __forceinline__ void ldsm_frags(Frags& f, uint32_t As, uint32_t Bs,
                                           int warp_m, int warp_n, int lane, int ks)
{
#pragma unroll
    for (int mf = 0; mf < 2; ++mf) {
        uint32_t ad = As + (uint32_t)((warp_m * 32 + mf * 16 + (lane & 15)) * 80
                                      + ((lane >> 4) << 4) + ks * 32);
        ldsm4(f.ah[mf], ad);
        ldsm4(f.al[mf], ad + TILE_B);
    }
#pragma unroll
    for (int n2 = 0; n2 < 4; ++n2) {
        uint32_t bd = Bs + (uint32_t)((warp_n * 64 + n2 * 16 + (lane & 15)) * 80
                                      + ((lane >> 4) << 4) + ks * 32);
        ldsm4(f.bh[n2], bd);
        ldsm4(f.bl[n2], bd + TILE_B);
    }
}

__device__ __forceinline__ void mma_block(float acc[2][8][4], const Frags& f)
{
    // term-major: 16 independent MMAs between revisits of an accumulator
#pragma unroll
    for (int mf = 0; mf < 2; ++mf)
#pragma unroll
        for (int nf = 0; nf < 8; ++nf)
            mma16816(acc[mf][nf], f.ah[mf], f.bh[nf >> 1][nf & 1], f.bh[nf >> 1][2 + (nf & 1)]);
#pragma unroll
    for (int mf = 0; mf < 2; ++mf)
#pragma unroll
        for (int nf = 0; nf < 8; ++nf)
            mma16816(acc[mf][nf], f.ah[mf], f.bl[nf >> 1][nf & 1], f.bl[nf >> 1][2 + (nf & 1)]);
#pragma unroll
    for (int mf = 0; mf < 2; ++mf)
#pragma unroll
        for (int nf = 0; nf < 8; ++nf)
            mma16816(acc[mf][nf], f.al[mf], f.bh[nf >> 1][nf & 1], f.bh[nf >> 1][2 + (nf & 1)]);
}

// Mainloop + stage accumulators into SMEM fp32 [128][132]; leaves smem synced.
__device__ __forceinline__ void gemm_body(
    uint8_t* smem, uint32_t sb, int tid, int K,
    const uint8_t* __restrict__ aHi, const uint8_t* __restrict__ aLo,
    const uint8_t* __restrict__ bHi, const uint8_t* __restrict__ bLo,
    size_t aOff, size_t bOff)
{
    const int lane = tid & 31;
    const int wid = tid >> 5;          // 0..7
    const int warp_m = wid >> 1;       // 0..3  (32 rows)
    const int warp_n = wid & 1;        // 0..1  (64 cols)

    float acc[2][8][4];
#pragma unroll
    for (int a = 0; a < 2; ++a)
#pragma unroll
        for (int b = 0; b < 8; ++b)
#pragma unroll
            for (int c = 0; c < 4; ++c) acc[a][b][c] = 0.0f;

    const int nkc = K >> 5;            // K / 32
    load_stage(sb, 0, tid, 0, K, aHi, aLo, bHi, bLo, aOff, bOff);

    Frags f;
    for (int kc = 0; kc < nkc; ++kc) {
        asm volatile("cp.async.wait_group 0;" ::: "memory");
        __syncthreads();   // publishes slot kc&1; other slot fully read last iter
        if (kc + 1 < nkc)
            load_stage(sb, (kc + 1) & 1, tid, kc + 1, K, aHi, aLo, bHi, bLo, aOff, bOff);

        const uint32_t As = sb + (uint32_t)(kc & 1) * STG;
        const uint32_t Bs = As + 2 * TILE_B;
#pragma unroll
        for (int ks = 0; ks < 2; ++ks) {
            ldsm_frags(f, As, Bs, warp_m, warp_n, lane, ks);
            mma_block(acc, f);
        }
    }
    asm volatile("cp.async.wait_group 0;" ::: "memory");
    __syncthreads();

    float* sf = (float*)smem;   // [128][132]
#pragma unroll
    for (int mf = 0; mf < 2; ++mf)
#pragma unroll
        for (int nf = 0; nf < 8; ++nf) {
            const int r0 = warp_m * 32 + mf * 16 + (lane >> 2);
            const int c0 = warp_n * 64 + nf * 8 + (lane & 3) * 2;
            sf[r0 * 132 + c0]           = acc[mf][nf][0];
            sf[r0 * 132 + c0 + 1]       = acc[mf][nf][1];
            sf[(r0 + 8) * 132 + c0]     = acc[mf][nf][2];
            sf[(r0 + 8) * 132 + c0 + 1] = acc[mf][nf][3];
        }
    __syncthreads();
}

// ---------------- fused projections: z=0 Q, z=1 K, z=2 V ---------------------
__global__ void __launch_bounds__(NTHR, 2)
proj_gemm(const uint8_t* __restrict__ pah, const uint8_t* __restrict__ pal,
          const uint8_t* __restrict__ pwh, const uint8_t* __restrict__ pwl,
          const float* __restrict__ b0, const float* __restrict__ b1,
          const float* __restrict__ b2,
          uint8_t* __restrict__ qh, uint8_t* __restrict__ ql,
          uint8_t* __restrict__ kh, uint8_t* __restrict__ kl,
          uint8_t* __restrict__ vth, uint8_t* __restrict__ vtl)
{
    extern __shared__ __align__(128) uint8_t smem[];
    const uint32_t sb = smem_u32(smem);
    const int tid = threadIdx.x;
    const int z = blockIdx.z;
    const int aBlk = blockIdx.y;                 // 0..63 over 8192 rows
    const int nBase = blockIdx.x * 128;          // 0..896

    const uint8_t* aHi = pah + (size_t)z * APS;
    const uint8_t* aLo = pal + (size_t)z * APS;
    const uint8_t* bHi = pwh + (size_t)z * WPS;
    const uint8_t* bLo = pwl + (size_t)z * WPS;
    const float* bias = (z == 0) ? b0 : (z == 1) ? b1 : b2;

    gemm_body(smem, sb, tid, 1024, aHi, aLo, bHi, bLo,
              (size_t)aBlk * 128 * 1024 * 2, (size_t)blockIdx.x * 128 * 1024 * 2);

    float* sf = (float*)smem;
    if (z < 2) {
        uint8_t* pHi = (z == 0) ? qh : kh;
        uint8_t* pLo = (z == 0) ? ql : kl;
        for (int idx = tid * 4; idx < 16384; idx += NTHR * 4) {
            const int r = idx >> 7, c = idx & 127;
            float4 x = *(const float4*)&sf[r * 132 + c];
            float v[4] = {x.x + bias[nBase + c],     x.y + bias[nBase + c + 1],
                          x.z + bias[nBase + c + 2], x.w + bias[nBase + c + 3]};
            unsigned long long H, L;
            split4(v, H, L);
            const size_t off = ((size_t)(aBlk * 128 + r) * 1024 + nBase + c) * 2;
            *(unsigned long long*)(pHi + off) = H;
            *(unsigned long long*)(pLo + off) = L;
        }
    } else {
        // transposed pack: v^T row = b*1024 + n, col = seq
        const int rowStart = aBlk * 128;
        const int b = rowStart >> 12;
        const int s0 = rowStart & 4095;
        for (int idx = tid * 4; idx < 16384; idx += NTHR * 4) {
            const int c = idx >> 7;      // embedding col local
            const int r = idx & 127;     // seq local (4 consecutive)
            const int gn = nBase + c;
            const float bv = bias[gn];
            float v[4];
#pragma unroll
            for (int i = 0; i < 4; ++i) v[i] = sf[(r + i) * 132 + c] + bv;
            unsigned long long H, L;
            split4(v, H, L);
            const size_t off = ((size_t)(b * 1024 + gn) * 4096 + s0 + r) * 2;
            *(unsigned long long*)(vth + off) = H;
            *(unsigned long long*)(vtl + off) = L;
        }
    }
}

// ---------------- scores GEMM: mask ? NINF : *SCALE, + block row-maxes -------
__global__ void __launch_bounds__(NTHR, 2)
score_gemm(const uint8_t* __restrict__ qh, const uint8_t* __restrict__ ql,
           const uint8_t* __restrict__ kh, const uint8_t* __restrict__ kl,
           const int* __restrict__ mask, float* __restrict__ outF,
           float* __restrict__ bmaxP)
{
    extern __shared__ __align__(128) uint8_t smem[];
    const uint32_t sb = smem_u32(smem);
    const int tid = threadIdx.x;
    const int lane = tid & 31;
    const int z = blockIdx.z;
    const int aBlk = z * 32 + blockIdx.y;
    const int bBlk = z * 32 + blockIdx.x;

    gemm_body(smem, sb, tid, 1024, qh, ql, kh, kl,
              (size_t)aBlk * 128 * 1024 * 2, (size_t)bBlk * 128 * 1024 * 2);

    float* sf = (float*)smem;
#pragma unroll 1
    for (int j = 0; j < 16; ++j) {
        const int idx = tid * 4 + NTHR * 4 * j;
        const int r = idx >> 7, c = idx & 127;     // 32 lanes cover one row
        const int mrow = blockIdx.y * 128 + r;
        const int gcol = blockIdx.x * 128 + c;
        const int4 mk = *(const int4*)(mask + (size_t)mrow * SQ + gcol);
        float4 x = *(const float4*)&sf[r * 132 + c];
        float4 o;
        o.x = mk.x ? NINF : x.x * SCALE;
        o.y = mk.y ? NINF : x.y * SCALE;
        o.z = mk.z ? NINF : x.z * SCALE;
        o.w = mk.w ? NINF : x.w * SCALE;
        *(float4*)(outF + ((size_t)(z * SQ + mrow)) * SQ + gcol) = o;
        float lm = fmaxf(fmaxf(o.x, o.y), fmaxf(o.z, o.w));
#pragma unroll
        for (int s = 16; s; s >>= 1)
            lm = fmaxf(lm, __shfl_xor_sync(0xffffffffu, lm, s));
        if (lane == 0)
            bmaxP[((size_t)(z * SQ + mrow) << 5) + blockIdx.x] = lm;
    }
}

// ---------------- PV GEMM: normalize by row sum ------------------------------
__global__ void __launch_bounds__(NTHR, 2)
pv_gemm(const uint8_t* __restrict__ ath, const uint8_t* __restrict__ atl,
        const uint8_t* __restrict__ vth, const uint8_t* __restrict__ vtl,
        const float* __restrict__ rsum, float* __restrict__ outF)
{
    extern __shared__ __align__(128) uint8_t smem[];
    const uint32_t sb = smem_u32(smem);
    const int tid = threadIdx.x;
    const int z = blockIdx.z;
    const int aBlk = z * 32 + blockIdx.y;      // attn rows (8192)
    const int bBlk = z * 8 + blockIdx.x;       // v^T rows (2048)

    gemm_body(smem, sb, tid, 4096, ath, atl, vth, vtl,
              (size_t)aBlk * 128 * 4096 * 2, (size_t)bBlk * 128 * 4096 * 2);

    float* sf = (float*)smem;
    for (int idx = tid * 4; idx < 16384; idx += NTHR * 4) {
        const int r = idx >> 7, c = idx & 127;
        const int mrow = blockIdx.y * 128 + r;
        const int gcol = blockIdx.x * 128 + c;
        const float inv = 1.0f / rsum[z * SQ + mrow];
        float4 o = *(const float4*)&sf[r * 132 + c];
        o.x *= inv; o.y *= inv; o.z *= inv; o.w *= inv;
        *(float4*)(outF + ((size_t)(z * SQ + mrow)) * EMB + gcol) = o;
    }
}

// ---------------- softmax: exp + pack (unnormalized) + row sum ---------------
__global__ void __launch_bounds__(256)
softmax_pack(const float* __restrict__ Sc, const float* __restrict__ bmax,
             float* __restrict__ rsum, uint8_t* __restrict__ hi, uint8_t* __restrict__ lo)
{
    __shared__ float red[256];
    const int row = blockIdx.x;                     // 0..8191 (global row)
    const float* p = Sc + (size_t)row * SQ;
    const int tid = threadIdx.x;

    float m = (tid < 32) ? bmax[((size_t)row << 5) + tid] : -3.4e38f;
    red[tid] = m; __syncthreads();
    for (int s = 128; s > 0; s >>= 1) {
        if (tid < s) red[tid] = fmaxf(red[tid], red[tid + s]);
        __syncthreads();
    }
    m = red[0]; __syncthreads();

    float sum = 0.0f;
    const size_t rowOff = (size_t)row * SQ;
    for (int j = tid * 4; j < SQ; j += 1024) {
        float4 x = *(const float4*)(p + j);
        float v[4] = {__expf(x.x - m), __expf(x.y - m),
                      __expf(x.z - m), __expf(x.w - m)};
        sum += v[0] + v[1] + v[2] + v[3];
        unsigned long long H, L;
        split4(v, H, L);
        *(unsigned long long*)(hi + (rowOff + j) * 2) = H;
        *(unsigned long long*)(lo + (rowOff + j) * 2) = L;
    }
    red[tid] = sum; __syncthreads();
    for (int s = 128; s > 0; s >>= 1) {
        if (tid < s) red[tid] += red[tid + s];
        __syncthreads();
    }
    if (tid == 0) rsum[row] = red[0];
}

// ============================================================================
extern "C" void kernel_launch(void* const* d_in, const int* in_sizes, int n_in,
                              void* d_out, int out_size)
{
    const float* query = (const float*)d_in[0];
    const float* key   = (const float*)d_in[1];
    const float* value = (const float*)d_in[2];
    const int*   mask  = (const int*)d_in[3];
    const float* Wq    = (const float*)d_in[4];
    const float* bq    = (const float*)d_in[5];
    const float* Wk    = (const float*)d_in[6];
    const float* bk    = (const float*)d_in[7];
    const float* Wv    = (const float*)d_in[8];
    const float* bv    = (const float*)d_in[9];
    float* out = (float*)d_out;

    cudaFuncSetAttribute((const void*)proj_gemm,  cudaFuncAttributeMaxDynamicSharedMemorySize, SMEM_SZ);
    cudaFuncSetAttribute((const void*)score_gemm, cudaFuncAttributeMaxDynamicSharedMemorySize, SMEM_SZ);
    cudaFuncSetAttribute((const void*)pv_gemm,    cudaFuncAttributeMaxDynamicSharedMemorySize, SMEM_SZ);

    uint8_t *pah, *pal, *pwh, *pwl;
    uint8_t *qhi, *qlo, *khi, *klo, *vthi, *vtlo, *athi, *atlo;
    float *sc, *bmax, *rsum;
    cudaGetSymbolAddress((void**)&pah,  g_pah);    cudaGetSymbolAddress((void**)&pal,  g_pal);
    cudaGetSymbolAddress((void**)&pwh,  g_pwh);    cudaGetSymbolAddress((void**)&pwl,  g_pwl);
    cudaGetSymbolAddress((void**)&qhi,  g_q_hi);   cudaGetSymbolAddress((void**)&qlo,  g_q_lo);
    cudaGetSymbolAddress((void**)&khi,  g_k_hi);   cudaGetSymbolAddress((void**)&klo,  g_k_lo);
    cudaGetSymbolAddress((void**)&vthi, g_vt_hi);  cudaGetSymbolAddress((void**)&vtlo, g_vt_lo);
    cudaGetSymbolAddress((void**)&athi, g_at_hi);  cudaGetSymbolAddress((void**)&atlo, g_at_lo);
    cudaGetSymbolAddress((void**)&sc,   g_sc);
    cudaGetSymbolAddress((void**)&bmax, g_bmax);
    cudaGetSymbolAddress((void**)&rsum, g_rsum);

    // ---- packs ----
    pack3<<<3 * 8192, 256>>>(query, key, value, pah, pal, APS, 8192);
    pack3<<<3 * 1024, 256>>>(Wq, Wk, Wv, pwh, pwl, WPS, 1024);

    // ---- fused projections (Q, K, V in one launch) ----
    dim3 gProj(8, 64, 3);
    proj_gemm<<<gProj, NTHR, SMEM_SZ>>>(pah, pal, pwh, pwl, bq, bk, bv,
                                        qhi, qlo, khi, klo, vthi, vtlo);

    // ---- scores = q k^T / 32 with mask (+ block row-maxes) ----
    dim3 gSc(32, 32, NB);
    score_gemm<<<gSc, NTHR, SMEM_SZ>>>(qhi, qlo, khi, klo, mask, sc, bmax);

    // ---- exp + pack (unnormalized) + row sums ----
    softmax_pack<<<NB * SQ, 256>>>(sc, bmax, rsum, athi, atlo);

    // ---- out = (exp @ v) / rowsum ----
    dim3 gAV(8, 32, NB);
    pv_gemm<<<gAV, NTHR, SMEM_SZ>>>(athi, atlo, vthi, vtlo, rsum, out);
}

// round 14
// speedup vs baseline: 1.6083x; 1.6083x over previous
#include <cuda_runtime.h>
#include <cuda_bf16.h>
#include <cstdint>

// ============================================================================
// ScaledDotProductAttention B=2, S=4096, E=1024 — mma.sync bf16 split-precision
// x = hi + lo (bf16);  A*B ~= Ah*Bh + Ah*Bl + Al*Bh  with fp32 accumulators.
// All GEMMs NT: C[m,n] = sum_k A[m,k] * B[n,k], operands row-major bf16 hi/lo.
// R13: revert to the R8 mainloop (16 warps, 4-stage ring, distance-3 refill,
// cross-iteration fragment prefetch — best measured: 1784us) after R10/R11
// showed 2-stage rings expose refill latency and co-residency doesn't fit
// with >=3 stages. Softmax rewritten with warp-shuffle reductions (512 thr).
// cp.async visibility rule (R6 NaN): every smem read happens after the
// __syncthreads that follows the wait_group covering that stage.
// ============================================================================

#define SQ    4096
#define EMB   1024
#define NB    2
#define NINF  -1000000000.0f
#define SCALE 0.03125f

#define APS ((size_t)8192 * 1024 * 2)   // one packed activation tensor
#define WPS ((size_t)1024 * 1024 * 2)   // one packed weight tensor

// ---------------- scratch (device globals; no allocation allowed) -----------
__device__ uint8_t g_pah[3 * APS];                    // packed q,k,v inputs (hi)
__device__ uint8_t g_pal[3 * APS];                    // (lo)
__device__ uint8_t g_pwh[3 * WPS];                    // packed Wq,Wk,Wv (hi)
__device__ uint8_t g_pwl[3 * WPS];                    // (lo)
__device__ uint8_t g_q_hi [APS];
__device__ uint8_t g_q_lo [APS];
__device__ uint8_t g_k_hi [APS];
__device__ uint8_t g_k_lo [APS];
__device__ uint8_t g_vt_hi[(size_t)2048 * 4096 * 2];  // v^T: row = b*1024+n, col = s
__device__ uint8_t g_vt_lo[(size_t)2048 * 4096 * 2];
__device__ float   g_sc   [(size_t)NB * SQ * SQ];     // fp32 masked scaled scores
__device__ float   g_bmax [(size_t)NB * SQ * 32];     // per-row per-128col-block max
__device__ float   g_rsum [(size_t)NB * SQ];          // per-row sum of exp
__device__ uint8_t g_at_hi[(size_t)8192 * 4096 * 2];  // packed unnormalized exp
__device__ uint8_t g_at_lo[(size_t)8192 * 4096 * 2];

// ---------------- helpers ----------------------------------------------------
__device__ __forceinline__ uint32_t smem_u32(const void* p) {
    uint32_t a;
    asm("{ .reg .u64 t; cvta.to.shared.u64 t, %1; cvt.u32.u64 %0, t; }" : "=r"(a) : "l"(p));
    return a;
}

__device__ __forceinline__ void cp16(uint32_t dst, const void* src) {
    asm volatile("cp.async.cg.shared.global [%0], [%1], 16;" :: "r"(dst), "l"(src));
}

__device__ __forceinline__ void ldsm4(uint32_t r[4], uint32_t addr) {
    asm volatile("ldmatrix.sync.aligned.m8n8.x4.shared.b16 {%0,%1,%2,%3}, [%4];"
        : "=r"(r[0]), "=r"(r[1]), "=r"(r[2]), "=r"(r[3]) : "r"(addr));
}

__device__ __forceinline__ void mma16816(float* c, const uint32_t a[4],
                                         uint32_t b0, uint32_t b1) {
    asm volatile("mma.sync.aligned.m16n8k16.row.col.f32.bf16.bf16.f32 "
        "{%0,%1,%2,%3}, {%4,%5,%6,%7}, {%8,%9}, {%0,%1,%2,%3};"
        : "+f"(c[0]), "+f"(c[1]), "+f"(c[2]), "+f"(c[3])
        : "r"(a[0]), "r"(a[1]), "r"(a[2]), "r"(a[3]), "r"(b0), "r"(b1));
}

__device__ __forceinline__ void split4(const float* v, unsigned long long& H,
                                       unsigned long long& L) {
    unsigned long long h = 0, l = 0;
#pragma unroll
    for (int i = 0; i < 4; ++i) {
        __nv_bfloat16 hb = __float2bfloat16(v[i]);
        float hf = __bfloat162float(hb);
        __nv_bfloat16 lb = __float2bfloat16(v[i] - hf);
        unsigned short hs = *reinterpret_cast<unsigned short*>(&hb);
        unsigned short ls = *reinterpret_cast<unsigned short*>(&lb);
        h |= (unsigned long long)hs << (16 * i);
        l |= (unsigned long long)ls << (16 * i);
    }
    H = h; L = l;
}

// ---------------- fused pack: 3 fp32 tensors -> bf16 hi/lo row-major ---------
__global__ void __launch_bounds__(256)
pack3(const float* __restrict__ s0, const float* __restrict__ s1, const float* __restrict__ s2,
      uint8_t* __restrict__ hiB, uint8_t* __restrict__ loB, size_t sliceBytes, int blocksPer)
{
    const int which = blockIdx.x / blocksPer;
    const int blk   = blockIdx.x - which * blocksPer;
    const float* src = (which == 0) ? s0 : (which == 1) ? s1 : s2;
    uint8_t* hi = hiB + (size_t)which * sliceBytes;
    uint8_t* lo = loB + (size_t)which * sliceBytes;
    size_t idx = ((size_t)blk * 256 + threadIdx.x) * 4;
    float4 x = *(const float4*)(src + idx);
    float v[4] = {x.x, x.y, x.z, x.w};
    unsigned long long H, L;
    split4(v, H, L);
    *(unsigned long long*)(hi + idx * 2) = H;
    *(unsigned long long*)(lo + idx * 2) = L;
}

// ---------------- the mma.sync GEMM mainloop ---------------------------------
// SMEM: 4 stages x 4 tiles (Ah, Al, Bh, Bl), each tile 128 rows x 80B (64B data).
#define TILE_B  10240
#define STG     40960
#define SMEM_SZ 163840   // 4 * STG; epilogue fp32 tile 128x132x4 = 67584 fits
#define NTHR    512

__device__ __forceinline__ void load_stage(
    uint32_t sb, int stage, int tid, int kc, int K,
    const uint8_t* aHi, const uint8_t* aLo,
    const uint8_t* bHi, const uint8_t* bLo,
    size_t aOff, size_t bOff)
{
    const uint32_t so = sb + (uint32_t)stage * STG;
    const int r = tid >> 2, c = tid & 3;
    const uint32_t soff = (uint32_t)(r * 80 + c * 16);
    const size_t goff = ((size_t)r * K + (size_t)kc * 32 + c * 8) * 2;
    cp16(so + soff,              aHi + aOff + goff);
    cp16(so + TILE_B + soff,     aLo + aOff + goff);
    cp16(so + 2 * TILE_B + soff, bHi + bOff + goff);
    cp16(so + 3 * TILE_B + soff, bLo + bOff + goff);
    asm volatile("cp.async.commit_group;" ::: "memory");
}

struct Frags { uint32_t ah[2][4], al[2][4], bh[2][4], bl[2][4]; };

__device__ __forceinline__ void ldsm_frags(Frags& f, uint32_t As, uint32_t Bs,
                                           int warp_m, int warp_n, int lane, int ks)
{
#pragma unroll
    for (int mf = 0; mf < 2; ++mf) {
        uint32_t ad = As + (uint32_t)((warp_m * 32 + mf * 16 + (lane & 15)) * 80
                                      + ((lane >> 4) << 4) + ks * 32);
        ldsm4(f.ah[mf], ad);
        ldsm4(f.al[mf], ad + TILE_B);
    }
#pragma unroll
    for (int n2 = 0; n2 < 2; ++n2) {
        uint32_t bd = Bs + (uint32_t)((warp_n * 32 + n2 * 16 + (lane & 15)) * 80
                                      + ((lane >> 4) << 4) + ks * 32);
        ldsm4(f.bh[n2], bd);
        ldsm4(f.bl[n2], bd + TILE_B);
    }
}

__device__ __forceinline__ void mma_block(float acc[2][4][4], const Frags& f)
{
    // term-major: 8 independent MMAs between revisits of an accumulator
#pragma unroll
    for (int mf = 0; mf < 2; ++mf)
#pragma unroll
        for (int nf = 0; nf < 4; ++nf)
            mma16816(acc[mf][nf], f.ah[mf], f.bh[nf >> 1][nf & 1], f.bh[nf >> 1][2 + (nf & 1)]);
#pragma unroll
    for (int mf = 0; mf < 2; ++mf)
#pragma unroll
        for (int nf = 0; nf < 4; ++nf)
            mma16816(acc[mf][nf], f.ah[mf], f.bl[nf >> 1][nf & 1], f.bl[nf >> 1][2 + (nf & 1)]);
#pragma unroll
    for (int mf = 0; mf < 2; ++mf)
#pragma unroll
        for (int nf = 0; nf < 4; ++nf)
            mma16816(acc[mf][nf], f.al[mf], f.bh[nf >> 1][nf & 1], f.bh[nf >> 1][2 + (nf & 1)]);
}

// Mainloop + stage accumulators into SMEM fp32 [128][132]; leaves smem synced.
__device__ __forceinline__ void gemm_body(
    uint8_t* smem, uint32_t sb, int tid, int K,
    const uint8_t* __restrict__ aHi, const uint8_t* __restrict__ aLo,
    const uint8_t* __restrict__ bHi, const uint8_t* __restrict__ bLo,
    size_t aOff, size_t bOff)
{
    const int lane = tid & 31;
    const int wid = tid >> 5;
    const int warp_m = wid >> 2;       // 0..3  (32 rows)
    const int warp_n = wid & 3;        // 0..3  (32 cols)

    float acc[2][4][4];
#pragma unroll
    for (int a = 0; a < 2; ++a)
#pragma unroll
        for (int b = 0; b < 4; ++b)
#pragma unroll
            for (int c = 0; c < 4; ++c) acc[a][b][c] = 0.0f;

    const int nkc = K >> 5;
    load_stage(sb, 0, tid, 0, K, aHi, aLo, bHi, bLo, aOff, bOff);
    load_stage(sb, 1, tid, 1, K, aHi, aLo, bHi, bLo, aOff, bOff);
    load_stage(sb, 2, tid, 2, K, aHi, aLo, bHi, bLo, aOff, bOff);

    Frags f0, f1;
    // preload f0 of kc=0 (stage 0 published by this barrier)
    asm volatile("cp.async.wait_group 2;" ::: "memory");
    __syncthreads();
    ldsm_frags(f0, sb, sb + 2 * TILE_B, warp_m, warp_n, lane, 0);

    for (int kc = 0; kc < nkc; ++kc) {
        // publish stages kc AND kc+1 (wait_group 1 leaves at most one group,
        // the one targeting stage kc+2, in flight)
        asm volatile("cp.async.wait_group 1;" ::: "memory");
        __syncthreads();   // also frees slot (kc-1)&3 for the refill below
        const uint32_t As  = sb + (uint32_t)(kc & 3) * STG;
        const uint32_t Bs  = As + 2 * TILE_B;
        const uint32_t AsN = sb + (uint32_t)((kc + 1) & 3) * STG;
        const uint32_t BsN = AsN + 2 * TILE_B;
        ldsm_frags(f1, As, Bs, warp_m, warp_n, lane, 1);
        if (kc + 3 < nkc)
            load_stage(sb, (kc + 3) & 3, tid, kc + 3, K, aHi, aLo, bHi, bLo, aOff, bOff);
        else
            asm volatile("cp.async.commit_group;" ::: "memory");
        mma_block(acc, f0);
        // prefetch next iteration's f0 (stage kc+1, published above) under the
        // f1 MMAs; last iteration reads stale data that is never consumed.
        ldsm_frags(f0, AsN, BsN, warp_m, warp_n, lane, 0);
        mma_block(acc, f1);
    }
    asm volatile("cp.async.wait_group 0;" ::: "memory");
    __syncthreads();

    float* sf = (float*)smem;   // [128][132]
#pragma unroll
    for (int mf = 0; mf < 2; ++mf)
#pragma unroll
        for (int nf = 0; nf < 4; ++nf) {
            const int r0 = warp_m * 32 + mf * 16 + (lane >> 2);
            const int c0 = warp_n * 32 + nf * 8 + (lane & 3) * 2;
            sf[r0 * 132 + c0]           = acc[mf][nf][0];
            sf[r0 * 132 + c0 + 1]       = acc[mf][nf][1];
            sf[(r0 + 8) * 132 + c0]     = acc[mf][nf][2];
            sf[(r0 + 8) * 132 + c0 + 1] = acc[mf][nf][3];
        }
    __syncthreads();
}

// ---------------- fused projections: z=0 Q, z=1 K, z=2 V ---------------------
__global__ void __launch_bounds__(NTHR)
proj_gemm(const uint8_t* __restrict__ pah, const uint8_t* __restrict__ pal,
          const uint8_t* __restrict__ pwh, const uint8_t* __restrict__ pwl,
          const float* __restrict__ b0, const float* __restrict__ b1,
          const float* __restrict__ b2,
          uint8_t* __restrict__ qh, uint8_t* __restrict__ ql,
          uint8_t* __restrict__ kh, uint8_t* __restrict__ kl,
          uint8_t* __restrict__ vth, uint8_t* __restrict__ vtl)
{
    extern __shared__ __align__(128) uint8_t smem[];
    const uint32_t sb = smem_u32(smem);
    const int tid = threadIdx.x;
    const int z = blockIdx.z;
    const int aBlk = blockIdx.y;                 // 0..63 over 8192 rows
    const int nBase = blockIdx.x * 128;          // 0..896

    const uint8_t* aHi = pah + (size_t)z * APS;
    const uint8_t* aLo = pal + (size_t)z * APS;
    const uint8_t* bHi = pwh + (size_t)z * WPS;
    const uint8_t* bLo = pwl + (size_t)z * WPS;
    const float* bias = (z == 0) ? b0 : (z == 1) ? b1 : b2;

    gemm_body(smem, sb, tid, 1024, aHi, aLo, bHi, bLo,
              (size_t)aBlk * 128 * 1024 * 2, (size_t)blockIdx.x * 128 * 1024 * 2);

    float* sf = (float*)smem;
    if (z < 2) {
        uint8_t* pHi = (z == 0) ? qh : kh;
        uint8_t* pLo = (z == 0) ? ql : kl;
        for (int idx = tid * 4; idx < 16384; idx += NTHR * 4) {
            const int r = idx >> 7, c = idx & 127;
            float4 x = *(const float4*)&sf[r * 132 + c];
            float v[4] = {x.x + bias[nBase + c],     x.y + bias[nBase + c + 1],
                          x.z + bias[nBase + c + 2], x.w + bias[nBase + c + 3]};
            unsigned long long H, L;
            split4(v, H, L);
            const size_t off = ((size_t)(aBlk * 128 + r) * 1024 + nBase + c) * 2;
            *(unsigned long long*)(pHi + off) = H;
            *(unsigned long long*)(pLo + off) = L;
        }
    } else {
        // transposed pack: v^T row = b*1024 + n, col = seq
        const int rowStart = aBlk * 128;
        const int b = rowStart >> 12;
        const int s0 = rowStart & 4095;
        for (int idx = tid * 4; idx < 16384; idx += NTHR * 4) {
            const int c = idx >> 7;      // embedding col local
            const int r = idx & 127;     // seq local (4 consecutive)
            const int gn = nBase + c;
            const float bv = bias[gn];
            float v[4];
#pragma unroll
            for (int i = 0; i < 4; ++i) v[i] = sf[(r + i) * 132 + c] + bv;
            unsigned long long H, L;
            split4(v, H, L);
            const size_t off = ((size_t)(b * 1024 + gn) * 4096 + s0 + r) * 2;
            *(unsigned long long*)(vth + off) = H;
            *(unsigned long long*)(vtl + off) = L;
        }
    }
}

// ---------------- scores GEMM: mask ? NINF : *SCALE, + block row-maxes -------
__global__ void __launch_bounds__(NTHR)
score_gemm(const uint8_t* __restrict__ qh, const uint8_t* __restrict__ ql,
           const uint8_t* __restrict__ kh, const uint8_t* __restrict__ kl,
           const int* __restrict__ mask, float* __restrict__ outF,
           float* __restrict__ bmaxP)
{
    extern __shared__ __align__(128) uint8_t smem[];
    const uint32_t sb = smem_u32(smem);
    const int tid = threadIdx.x;
    const int lane = tid & 31;
    const int z = blockIdx.z;
    const int aBlk = z * 32 + blockIdx.y;
    const int bBlk = z * 32 + blockIdx.x;

    gemm_body(smem, sb, tid, 1024, qh, ql, kh, kl,
              (size_t)aBlk * 128 * 1024 * 2, (size_t)bBlk * 128 * 1024 * 2);

    float* sf = (float*)smem;
#pragma unroll 1
    for (int j = 0; j < 8; ++j) {
        const int idx = tid * 4 + NTHR * 4 * j;
        const int r = idx >> 7, c = idx & 127;     // 32 lanes cover one row
        const int mrow = blockIdx.y * 128 + r;
        const int gcol = blockIdx.x * 128 + c;
        const int4 mk = *(const int4*)(mask + (size_t)mrow * SQ + gcol);
        float4 x = *(const float4*)&sf[r * 132 + c];
        float4 o;
        o.x = mk.x ? NINF : x.x * SCALE;
        o.y = mk.y ? NINF : x.y * SCALE;
        o.z = mk.z ? NINF : x.z * SCALE;
        o.w = mk.w ? NINF : x.w * SCALE;
        *(float4*)(outF + ((size_t)(z * SQ + mrow)) * SQ + gcol) = o;
        float lm = fmaxf(fmaxf(o.x, o.y), fmaxf(o.z, o.w));
#pragma unroll
        for (int s = 16; s; s >>= 1)
            lm = fmaxf(lm, __shfl_xor_sync(0xffffffffu, lm, s));
        if (lane == 0)
            bmaxP[((size_t)(z * SQ + mrow) << 5) + blockIdx.x] = lm;
    }
}

// ---------------- PV GEMM: normalize by row sum ------------------------------
__global__ void __launch_bounds__(NTHR)
pv_gemm(const uint8_t* __restrict__ ath, const uint8_t* __restrict__ atl,
        const uint8_t* __restrict__ vth, const uint8_t* __restrict__ vtl,
        const float* __restrict__ rsum, float* __restrict__ outF)
{
    extern __shared__ __align__(128) uint8_t smem[];
    const uint32_t sb = smem_u32(smem);
    const int tid = threadIdx.x;
    const int z = blockIdx.z;
    const int aBlk = z * 32 + blockIdx.y;      // attn rows (8192)
    const int bBlk = z * 8 + blockIdx.x;       // v^T rows (2048)

    gemm_body(smem, sb, tid, 4096, ath, atl, vth, vtl,
              (size_t)aBlk * 128 * 4096 * 2, (size_t)bBlk * 128 * 4096 * 2);

    float* sf = (float*)smem;
    for (int idx = tid * 4; idx < 16384; idx += NTHR * 4) {
        const int r = idx >> 7, c = idx & 127;
        const int mrow = blockIdx.y * 128 + r;
        const int gcol = blockIdx.x * 128 + c;
        const float inv = 1.0f / rsum[z * SQ + mrow];
        float4 o = *(const float4*)&sf[r * 132 + c];
        o.x *= inv; o.y *= inv; o.z *= inv; o.w *= inv;
        *(float4*)(outF + ((size_t)(z * SQ + mrow)) * EMB + gcol) = o;
    }
}

// ---------------- softmax: exp + pack (unnormalized) + row sum ---------------
// 512 threads/row, warp-shuffle reductions (2 barriers instead of 8 trees).
__global__ void __launch_bounds__(512)
softmax_pack(const float* __restrict__ Sc, const float* __restrict__ bmax,
             float* __restrict__ rsum, uint8_t* __restrict__ hi, uint8_t* __restrict__ lo)
{
    __shared__ float smax;
    __shared__ float swarp[16];
    const int row = blockIdx.x;                     // 0..8191 (global row)
    const float* p = Sc + (size_t)row * SQ;
    const int tid = threadIdx.x;
    const int lane = tid & 31, wid = tid >> 5;

    if (wid == 0) {
        float m = bmax[((size_t)row << 5) + lane];
#pragma unroll
        for (int s = 16; s; s >>= 1) m = fmaxf(m, __shfl_xor_sync(0xffffffffu, m, s));
        if (lane == 0) smax = m;
    }
    __syncthreads();
    const float m = smax;

    float sum = 0.0f;
    const size_t rowOff = (size_t)row * SQ;
#pragma unroll
    for (int it = 0; it < 2; ++it) {
        const int j = (tid + it * 512) * 4;
        float4 x = *(const float4*)(p + j);
        float v[4] = {__expf(x.x - m), __expf(x.y - m),
                      __expf(x.z - m), __expf(x.w - m)};
        sum += v[0] + v[1] + v[2] + v[3];
        unsigned long long H, L;
        split4(v, H, L);
        *(unsigned long long*)(hi + (rowOff + j) * 2) = H;
        *(unsigned long long*)(lo + (rowOff + j) * 2) = L;
    }
#pragma unroll
    for (int s = 16; s; s >>= 1) sum += __shfl_xor_sync(0xffffffffu, sum, s);
    if (lane == 0) swarp[wid] = sum;
    __syncthreads();
    if (wid == 0) {
        float t = (lane < 16) ? swarp[lane] : 0.0f;
#pragma unroll
        for (int s = 8; s; s >>= 1) t += __shfl_xor_sync(0xffffffffu, t, s);
        if (lane == 0) rsum[row] = t;
    }
}

// ============================================================================
extern "C" void kernel_launch(void* const* d_in, const int* in_sizes, int n_in,
                              void* d_out, int out_size)
{
    const float* query = (const float*)d_in[0];
    const float* key   = (const float*)d_in[1];
    const float* value = (const float*)d_in[2];
    const int*   mask  = (const int*)d_in[3];
    const float* Wq    = (const float*)d_in[4];
    const float* bq    = (const float*)d_in[5];
    const float* Wk    = (const float*)d_in[6];
    const float* bk    = (const float*)d_in[7];
    const float* Wv    = (const float*)d_in[8];
    const float* bv    = (const float*)d_in[9];
    float* out = (float*)d_out;

    cudaFuncSetAttribute((const void*)proj_gemm,  cudaFuncAttributeMaxDynamicSharedMemorySize, SMEM_SZ);
    cudaFuncSetAttribute((const void*)score_gemm, cudaFuncAttributeMaxDynamicSharedMemorySize, SMEM_SZ);
    cudaFuncSetAttribute((const void*)pv_gemm,    cudaFuncAttributeMaxDynamicSharedMemorySize, SMEM_SZ);

    uint8_t *pah, *pal, *pwh, *pwl;
    uint8_t *qhi, *qlo, *khi, *klo, *vthi, *vtlo, *athi, *atlo;
    float *sc, *bmax, *rsum;
    cudaGetSymbolAddress((void**)&pah,  g_pah);    cudaGetSymbolAddress((void**)&pal,  g_pal);
    cudaGetSymbolAddress((void**)&pwh,  g_pwh);    cudaGetSymbolAddress((void**)&pwl,  g_pwl);
    cudaGetSymbolAddress((void**)&qhi,  g_q_hi);   cudaGetSymbolAddress((void**)&qlo,  g_q_lo);
    cudaGetSymbolAddress((void**)&khi,  g_k_hi);   cudaGetSymbolAddress((void**)&klo,  g_k_lo);
    cudaGetSymbolAddress((void**)&vthi, g_vt_hi);  cudaGetSymbolAddress((void**)&vtlo, g_vt_lo);
    cudaGetSymbolAddress((void**)&athi, g_at_hi);  cudaGetSymbolAddress((void**)&atlo, g_at_lo);
    cudaGetSymbolAddress((void**)&sc,   g_sc);
    cudaGetSymbolAddress((void**)&bmax, g_bmax);
    cudaGetSymbolAddress((void**)&rsum, g_rsum);

    // ---- packs ----
    pack3<<<3 * 8192, 256>>>(query, key, value, pah, pal, APS, 8192);
    pack3<<<3 * 1024, 256>>>(Wq, Wk, Wv, pwh, pwl, WPS, 1024);

    // ---- fused projections (Q, K, V in one launch) ----
    dim3 gProj(8, 64, 3);
    proj_gemm<<<gProj, NTHR, SMEM_SZ>>>(pah, pal, pwh, pwl, bq, bk, bv,
                                        qhi, qlo, khi, klo, vthi, vtlo);

    // ---- scores = q k^T / 32 with mask (+ block row-maxes) ----
    dim3 gSc(32, 32, NB);
    score_gemm<<<gSc, NTHR, SMEM_SZ>>>(qhi, qlo, khi, klo, mask, sc, bmax);

    // ---- exp + pack (unnormalized) + row sums ----
    softmax_pack<<<NB * SQ, 512>>>(sc, bmax, rsum, athi, atlo);

    // ---- out = (exp @ v) / rowsum ----
    dim3 gAV(8, 32, NB);
    pv_gemm<<<gAV, NTHR, SMEM_SZ>>>(athi, atlo, vthi, vtlo, rsum, out);
}